// round 13
// baseline (speedup 1.0000x reference)
#include <cuda_runtime.h>
#include <math_constants.h>

#define N_DEC 16
#define M_LEN 128
#define V_VOC 64
#define H_DIM 128
#define K_TPL 8
#define NP1 17
#define ROWS 136
#define MAXB 4096

// scratch between kernels
__device__ int g_src[MAXB * K_TPL];   // decodings row (sel-1) within b, or -1
__device__ int g_eff[MAXB * K_TPL];
__device__ int g_off[MAXB * K_TPL];

__device__ __forceinline__ float fmax4(float4 v) {
    return fmaxf(fmaxf(v.x, v.y), fmaxf(v.z, v.w));
}

// ---------------- Kernel 1: GEMV selection || speculative length scan ----------------
// 512 threads: warps 0-7 GEMV template k=warp; warps 8-15 scan rows 2w,2w+1
// (backward, early-exit: reads only the last 16-position chunk w.p. ~1-(1/64)^16).
__global__ __launch_bounds__(512, 2)
void select_len_kernel(
    const float* __restrict__ decodings,   // [B,16,128,64]
    const float* __restrict__ type_emb,    // [24,128]
    const float* __restrict__ w_sem,       // [15,136,128]
    const float* __restrict__ b_sem,       // [15,136]
    const float* __restrict__ gumbel,      // [B,8,17]
    const int*   __restrict__ target_types,// [B]
    const int*   __restrict__ spans)       // [B]
{
    const int b    = blockIdx.x;
    const int tid  = threadIdx.x;
    const int lane = tid & 31;
    const int w    = tid >> 5;

    __shared__ int s_sel[K_TPL];
    __shared__ int s_rowlen[N_DEC];

    const float* __restrict__ dec = decodings + (size_t)b * N_DEC * M_LEN * V_VOC;
    const int t = target_types[b];

    if (w >= 8) {
        // ---- speculative backward length scan of rows 2*(w-8), 2*(w-8)+1 ----
        const int half = lane & 1;
        const int mloc = lane >> 1;
        #pragma unroll 1
        for (int rr = 0; rr < 2; rr++) {
            const int r = (w - 8) * 2 + rr;
            const float4* __restrict__ row4 =
                (const float4*)(dec + (size_t)r * (M_LEN * V_VOC));
            int len = 0;
            #pragma unroll 1
            for (int c = 7; c >= 0; c--) {
                const int m = c * 16 + mloc;
                const float4* p4 = row4 + m * 16 + (half << 3);
                float4 x0 = p4[0], x1 = p4[1], x2 = p4[2], x3 = p4[3];
                float4 x4 = p4[4], x5 = p4[5], x6 = p4[6], x7 = p4[7];
                float cm = fmaxf(fmaxf(fmax4(x1), fmax4(x2)), fmaxf(fmax4(x3), fmax4(x4)));
                cm = fmaxf(cm, fmaxf(fmax4(x5), fmaxf(fmax4(x6), fmax4(x7))));
                float d0 = -CUDART_INF_F;
                if (half == 0) {          // x0.x is d[m,0]: excluded from candidate max
                    d0 = x0.x;
                    cm = fmaxf(cm, fmaxf(fmaxf(x0.y, x0.z), x0.w));
                } else {
                    cm = fmaxf(cm, fmax4(x0));
                }
                float cmp = fmaxf(cm, __shfl_xor_sync(0xffffffffu, cm, 1));
                float d0b = __shfl_sync(0xffffffffu, d0, lane & 0x1e);
                unsigned bal = __ballot_sync(0xffffffffu, cmp > d0b);
                if (bal) {                // warp-uniform ballot
                    int hb = 31 - __clz(bal);
                    len = c * 16 + (hb >> 1) + 1;   // token 0 wins ties
                    break;
                }
            }
            if (lane == 0) s_rowlen[r] = len;
        }
    } else {
        // ---- GEMV + gumbel argmax for template k = w ----
        const int k = w;
        if (t == 20) {
            if (lane == 0) s_sel[k] = (k == 0) ? 1 : 0;
        } else {
            const int ti = t - 9;
            const int span = spans[b];
            const float4 e = ((const float4*)(type_emb + t * H_DIM))[lane];
            const float4* __restrict__ w4 = (const float4*)
                (w_sem + ((size_t)ti * ROWS + k * NP1) * H_DIM);

            float add = 0.f;
            if (lane < NP1)
                add = b_sem[(size_t)ti * ROWS + k * NP1 + lane]
                    + gumbel[((size_t)b * K_TPL + k) * NP1 + lane];

            float p[NP1];
            #pragma unroll
            for (int n = 0; n < NP1; n++) {
                float4 wv = w4[n * 32 + lane];
                p[n] = wv.x * e.x + wv.y * e.y + wv.z * e.z + wv.w * e.w;
            }
            #pragma unroll
            for (int o = 16; o; o >>= 1) {
                #pragma unroll
                for (int n = 0; n < NP1; n++)
                    p[n] += __shfl_xor_sync(0xffffffffu, p[n], o);
            }
            float best = -CUDART_INF_F;
            int   bestn = 0;
            #pragma unroll
            for (int n = 0; n < NP1; n++) {
                float val = p[n] + __shfl_sync(0xffffffffu, add, n);
                if (n <= span && val > best) { best = val; bestn = n; }  // first-max
            }
            if (lane == 0) s_sel[k] = bestn;
        }
    }
    __syncthreads();

    if (tid == 0) {
        int cur = 0;
        #pragma unroll
        for (int kk = 0; kk < K_TPL; kk++) {
            const int sel = s_sel[kk];
            const int len = (sel > 0) ? s_rowlen[sel - 1] : 0;
            const int eff = min(len, M_LEN - cur);
            g_src[b * K_TPL + kk] = (sel > 0) ? (b * N_DEC + sel - 1) : -1;
            g_eff[b * K_TPL + kk] = eff;
            g_off[b * K_TPL + kk] = cur;
            cur += eff;
        }
        __threadfence();                  // make scratch visible before PDL trigger
    }
    __syncthreads();
#if __CUDA_ARCH__ >= 900
    cudaTriggerProgrammaticLaunchCompletion();
#endif
}

// ---------------- Kernel 2: gather-style packed copy, 4 blocks per batch elem ----------------
__global__ __launch_bounds__(256, 8)
void pack_gather_kernel(
    const float* __restrict__ decodings,   // [B,16,128,64]
    float*       __restrict__ out)         // [B,128,64]
{
    const int b    = blockIdx.x;
    const int part = blockIdx.y;           // 0..3: 32 output positions each
    const int tid  = threadIdx.x;

    // dependency-free prologue
    const float4* __restrict__ dec4 = (const float4*)decodings;
    float4* __restrict__ out4 = (float4*)out + (size_t)b * (M_LEN * 16) + part * 512;

    __shared__ int s_off[K_TPL], s_eff[K_TPL], s_src[K_TPL];

#if __CUDA_ARCH__ >= 900
    cudaGridDependencySynchronize();       // wait for K1 scratch
#endif
    if (tid < K_TPL) {
        s_off[tid] = g_off[b * K_TPL + tid];
        s_eff[tid] = g_eff[b * K_TPL + tid];
        s_src[tid] = g_src[b * K_TPL + tid];
    }
    __syncthreads();

    #pragma unroll
    for (int j = 0; j < 2; j++) {
        const int i = tid + j * 256;         // local float4 index in [0, 512)
        const int m = (part * 512 + i) >> 4; // output position
        const int c = i & 15;
        int srow = -1, sp = 0;
        #pragma unroll
        for (int kk = 0; kk < K_TPL; kk++) {
            const int o = s_off[kk];
            if (m >= o && m < o + s_eff[kk]) { srow = s_src[kk]; sp = m - o; }
        }
        float4 v = make_float4(0.f, 0.f, 0.f, 0.f);
        if (srow >= 0)
            v = dec4[(size_t)srow * (M_LEN * 16) + sp * 16 + c];
        out4[i] = v;
    }
}

extern "C" void kernel_launch(void* const* d_in, const int* in_sizes, int n_in,
                              void* d_out, int out_size)
{
    const float* decodings    = (const float*)d_in[0];
    const float* type_emb     = (const float*)d_in[1];
    const float* w_sem        = (const float*)d_in[2];
    const float* b_sem        = (const float*)d_in[3];
    const float* gumbel       = (const float*)d_in[4];
    const int*   target_types = (const int*)  d_in[5];
    const int*   spans        = (const int*)  d_in[6];
    float*       out          = (float*)d_out;

    const int B = in_sizes[5];

    select_len_kernel<<<B, 512>>>(decodings, type_emb, w_sem, b_sem,
                                  gumbel, target_types, spans);

    // PDL launch of the pack kernel: overlaps its prologue with K1's epilogue.
    cudaLaunchConfig_t cfg = {};
    cfg.gridDim  = dim3((unsigned)B, 4, 1);
    cfg.blockDim = dim3(256, 1, 1);
    cudaLaunchAttribute attr[1];
    attr[0].id = cudaLaunchAttributeProgrammaticStreamSerialization;
    attr[0].val.programmaticStreamSerializationAllowed = 1;
    cfg.attrs = attr;
    cfg.numAttrs = 1;
    cudaLaunchKernelEx(&cfg, pack_gather_kernel, decodings, out);
}

// round 15
// speedup vs baseline: 1.5135x; 1.5135x over previous
#include <cuda_runtime.h>
#include <math_constants.h>

#define N_DEC 16
#define M_LEN 128
#define V_VOC 64
#define H_DIM 128
#define K_TPL 8
#define NP1 17
#define ROWS 136
#define MAXB 4096

// scratch between kernels
__device__ int g_srcrow[MAXB * K_TPL];   // selected row (sel-1) within b, or -1
__device__ int g_len[MAXB * K_TPL];      // raw length (pre-clip)

__device__ __forceinline__ float fmax4(float4 v) {
    return fmaxf(fmaxf(v.x, v.y), fmaxf(v.z, v.w));
}

// ---------------- Kernel 1: one warp per (template k, batch b) ----------------
// GEMV over 17 candidates (replicated result in all lanes -> no smem, no sync),
// then backward early-exit length scan of the selected row (reads last 16-pos
// chunk w.p. ~1-(1/64)^16).
__global__ __launch_bounds__(32, 32)
void select_len_kernel(
    const float* __restrict__ decodings,   // [B,16,128,64]
    const float* __restrict__ type_emb,    // [24,128]
    const float* __restrict__ w_sem,       // [15,136,128]
    const float* __restrict__ b_sem,       // [15,136]
    const float* __restrict__ gumbel,      // [B,8,17]
    const int*   __restrict__ target_types,// [B]
    const int*   __restrict__ spans)       // [B]
{
    const int k    = blockIdx.x;           // template row 0..7
    const int b    = blockIdx.y;
    const int lane = threadIdx.x;

    const int t = target_types[b];

    // ---- selection ----
    int sel;
    if (t == 20) {
        sel = (k == 0) ? 1 : 0;
    } else {
        const int ti = t - 9;
        const int span = spans[b];
        const float4 e = ((const float4*)(type_emb + t * H_DIM))[lane];
        const float4* __restrict__ w4 = (const float4*)
            (w_sem + ((size_t)ti * ROWS + k * NP1) * H_DIM);

        float add = 0.f;
        if (lane < NP1)
            add = b_sem[(size_t)ti * ROWS + k * NP1 + lane]
                + gumbel[((size_t)b * K_TPL + k) * NP1 + lane];

        // 17 independent partial dots -> batched butterfly (17-wide ILP)
        float p[NP1];
        #pragma unroll
        for (int n = 0; n < NP1; n++) {
            float4 wv = w4[n * 32 + lane];
            p[n] = wv.x * e.x + wv.y * e.y + wv.z * e.z + wv.w * e.w;
        }
        #pragma unroll
        for (int o = 16; o; o >>= 1) {
            #pragma unroll
            for (int n = 0; n < NP1; n++)
                p[n] += __shfl_xor_sync(0xffffffffu, p[n], o);
        }
        // all lanes hold identical sums -> replicated argmax (first-max tiebreak)
        float best = -CUDART_INF_F;
        int   bestn = 0;
        #pragma unroll
        for (int n = 0; n < NP1; n++) {
            float val = p[n] + __shfl_sync(0xffffffffu, add, n);
            if (n <= span && val > best) { best = val; bestn = n; }
        }
        sel = bestn;
    }

    // ---- backward early-exit length scan of the selected row ----
    int len = 0;
    if (sel > 0) {
        const float4* __restrict__ row4 = (const float4*)
            (decodings + ((size_t)b * N_DEC + (sel - 1)) * (M_LEN * V_VOC));
        const int half = lane & 1;       // which 8-float4 half of the position
        const int mloc = lane >> 1;      // 16 positions per chunk

        #pragma unroll 1
        for (int c = 7; c >= 0; c--) {
            const int m = c * 16 + mloc;
            const float4* p4 = row4 + m * 16 + (half << 3);
            float4 x0 = p4[0], x1 = p4[1], x2 = p4[2], x3 = p4[3];
            float4 x4 = p4[4], x5 = p4[5], x6 = p4[6], x7 = p4[7];
            float cm = fmaxf(fmaxf(fmax4(x1), fmax4(x2)), fmaxf(fmax4(x3), fmax4(x4)));
            cm = fmaxf(cm, fmaxf(fmax4(x5), fmaxf(fmax4(x6), fmax4(x7))));
            float d0 = -CUDART_INF_F;
            if (half == 0) {             // x0.x is d[m,0]: excluded from candidate max
                d0 = x0.x;
                cm = fmaxf(cm, fmaxf(fmaxf(x0.y, x0.z), x0.w));
            } else {
                cm = fmaxf(cm, fmax4(x0));
            }
            float cmp = fmaxf(cm, __shfl_xor_sync(0xffffffffu, cm, 1));
            float d0b = __shfl_sync(0xffffffffu, d0, lane & 0x1e);
            unsigned bal = __ballot_sync(0xffffffffu, cmp > d0b);
            if (bal) {                   // warp-uniform
                int hb = 31 - __clz(bal);
                len = c * 16 + (hb >> 1) + 1;     // token 0 wins ties
                break;
            }
        }
    }

    if (lane == 0) {
        g_srcrow[b * K_TPL + k] = (sel > 0) ? (sel - 1) : -1;
        g_len[b * K_TPL + k]    = len;
    }
}

// ---------------- Kernel 2: gather-style packed copy, 4 blocks per batch elem ----------------
__global__ __launch_bounds__(256, 8)
void pack_gather_kernel(
    const float* __restrict__ decodings,   // [B,16,128,64]
    float*       __restrict__ out)         // [B,128,64]
{
    const int b    = blockIdx.x;
    const int part = blockIdx.y;           // 0..3: 32 output positions each
    const int tid  = threadIdx.x;

    __shared__ int s_src[K_TPL], s_len[K_TPL];
    if (tid < K_TPL) {
        s_src[tid] = g_srcrow[b * K_TPL + tid];
        s_len[tid] = g_len[b * K_TPL + tid];
    }
    __syncthreads();

    // offsets: tiny per-thread prefix (registers)
    int off8[K_TPL], eff8[K_TPL];
    {
        int cur = 0;
        #pragma unroll
        for (int kk = 0; kk < K_TPL; kk++) {
            const int e = min(s_len[kk], M_LEN - cur);
            off8[kk] = cur; eff8[kk] = e;
            cur += e;
        }
    }

    const float4* __restrict__ dec4 =
        (const float4*)decodings + (size_t)b * (N_DEC * M_LEN * 16);
    float4* __restrict__ out4 = (float4*)out + (size_t)b * (M_LEN * 16) + part * 512;

    #pragma unroll
    for (int j = 0; j < 2; j++) {
        const int i = tid + j * 256;         // local float4 index in [0, 512)
        const int m = (part * 512 + i) >> 4; // output position
        const int c = i & 15;
        int srow = -1, sp = 0;
        #pragma unroll
        for (int kk = 0; kk < K_TPL; kk++) {
            if (m >= off8[kk] && m < off8[kk] + eff8[kk]) {
                srow = s_src[kk]; sp = m - off8[kk];
            }
        }
        float4 v = make_float4(0.f, 0.f, 0.f, 0.f);
        if (srow >= 0)
            v = dec4[(size_t)srow * (M_LEN * 16) + sp * 16 + c];
        out4[i] = v;
    }
}

extern "C" void kernel_launch(void* const* d_in, const int* in_sizes, int n_in,
                              void* d_out, int out_size)
{
    const float* decodings    = (const float*)d_in[0];
    const float* type_emb     = (const float*)d_in[1];
    const float* w_sem        = (const float*)d_in[2];
    const float* b_sem        = (const float*)d_in[3];
    const float* gumbel       = (const float*)d_in[4];
    const int*   target_types = (const int*)  d_in[5];
    const int*   spans        = (const int*)  d_in[6];
    float*       out          = (float*)d_out;

    const int B = in_sizes[5];

    dim3 grid1(K_TPL, B);
    select_len_kernel<<<grid1, 32>>>(decodings, type_emb, w_sem, b_sem,
                                     gumbel, target_types, spans);
    dim3 grid2(B, 4);
    pack_gather_kernel<<<grid2, 256>>>(decodings, out);
}